// round 16
// baseline (speedup 1.0000x reference)
#include <cuda_runtime.h>
#include <cuda_fp16.h>
#include <cstdint>

#define BATCH 512
#define SEQ   512
#define EMB   128
#define FILT  128
#define KW    3
#define NCLS  53
#define VOCAB 21128
#define NBLK  (BATCH * 8)          // 4096 blocks of 64 l
#define R_RING 130                 // ring rows per group

// ---- smem layout (bytes, relative to 256B-aligned base) ----
#define WS_OFF   0                 // W fp16 [3][128 f][128 e], resident, chunk-swizzled
#define WS_BYTES 98304
#define XR_BYTES (R_RING * 256)    // 33280 per group ring
#define XR_OFF(g) (WS_BYTES + (g) * XR_BYTES)
#define MBAR_OFF (WS_BYTES + 4 * XR_BYTES)   // 231424
#define SMEM_BYTES (MBAR_OFF + 64 + 256)     // 231744 (<= 232448), incl. align slack

// pre-swizzled fp16 weights: g_Wh[k*16384 + f*128 + ((e>>3)^(f&7))*8 + (e&7)]
__device__ __align__(16) __half g_Wh[KW * FILT * EMB];
// fp16 embedding table (row-major, 256B rows)
__device__ __align__(16) __half g_EmbH[VOCAB * EMB];
// global segment-max pool: [batch][3][128] as float bits (zeroed in prep)
__device__ __align__(16) unsigned g_Pool[BATCH * 3 * FILT];

__device__ __forceinline__ uint32_t smem_u32(const void* p) {
    uint32_t a;
    asm("{ .reg .u64 t; cvta.to.shared.u64 t, %1; cvt.u32.u64 %0, t; }" : "=r"(a) : "l"(p));
    return a;
}

#define MBAR_INIT(a, c) asm volatile("mbarrier.init.shared.b64 [%0], %1;" :: "r"(a), "r"(c) : "memory")
#define MBAR_EXPECT_TX(a, n) asm volatile("mbarrier.arrive.expect_tx.shared.b64 _, [%0], %1;" :: "r"(a), "r"(n) : "memory")
#define MBAR_WAIT(a, p) do { \
    uint32_t _m = (a); uint32_t _p = (p); \
    asm volatile("{\n\t.reg .pred P;\n\tWL_%=:\n\t" \
        "mbarrier.try_wait.parity.acquire.cta.shared::cta.b64 P, [%0], %1, 0x989680;\n\t" \
        "@P bra.uni WD_%=;\n\tbra.uni WL_%=;\n\tWD_%=:\n\t}" :: "r"(_m), "r"(_p) : "memory"); \
} while (0)

#define BULK_G2S(dst, src, nbytes, mbar) \
    asm volatile("cp.async.bulk.shared::cluster.global.mbarrier::complete_tx::bytes [%0], [%1], %2, [%3];" \
        :: "r"(dst), "l"(src), "r"(nbytes), "r"(mbar) : "memory")

#define CP_ASYNC16(dst, src, srcsz) \
    asm volatile("cp.async.ca.shared.global [%0], [%1], 16, %2;" \
        :: "r"(dst), "l"(src), "r"(srcsz) : "memory")
#define CP_COMMIT() asm volatile("cp.async.commit_group;" ::: "memory")
#define CP_WAIT0()  asm volatile("cp.async.wait_group 0;" ::: "memory")

#define GBAR(g) asm volatile("bar.sync %0, 128;" :: "r"((g) + 1) : "memory")

#define LDSM_X4(r0, r1, r2, r3, a) \
    asm volatile("ldmatrix.sync.aligned.m8n8.x4.shared.b16 {%0,%1,%2,%3}, [%4];" \
        : "=r"(r0), "=r"(r1), "=r"(r2), "=r"(r3) : "r"(a))

#define MMA16816(c, a, b0, b1) \
    asm volatile("mma.sync.aligned.m16n8k16.row.col.f32.f16.f16.f32 " \
        "{%0,%1,%2,%3}, {%4,%5,%6,%7}, {%8,%9}, {%0,%1,%2,%3};" \
        : "+f"((c)[0]), "+f"((c)[1]), "+f"((c)[2]), "+f"((c)[3]) \
        : "r"((a)[0]), "r"((a)[1]), "r"((a)[2]), "r"((a)[3]), "r"(b0), "r"(b1))

// ---------------- combined prep: W swizzle + emb fp16 + pool zero ----------------
__global__ void prep_kernel(const float* __restrict__ conv_w,
                            const float* __restrict__ emb) {
    int idx = blockIdx.x * blockDim.x + threadIdx.x;
    if (idx < KW * FILT * EMB) {       // 49152: weight convert+swizzle
        int k = idx / (FILT * EMB);
        int rem = idx - k * FILT * EMB;
        int f = rem >> 7, e = rem & 127;
        float w = conv_w[(f * EMB + e) * KW + k];
        int dst = k * 16384 + f * 128 + (((e >> 3) ^ (f & 7)) << 3) + (e & 7);
        g_Wh[dst] = __float2half_rn(w);
        ((uint4*)g_Pool)[idx] = make_uint4(0u, 0u, 0u, 0u);  // 49152 uint4 = pool
    }
    if (idx < VOCAB * EMB / 4) {       // emb fp32 -> fp16
        const float4 x = __ldg((const float4*)emb + idx);
        __half2 h0 = __floats2half2_rn(x.x, x.y);
        __half2 h1 = __floats2half2_rn(x.z, x.w);
        uint2 st;
        st.x = *(uint32_t*)&h0; st.y = *(uint32_t*)&h1;
        *((uint2*)g_EmbH + idx) = st;
    }
}

// ---------------- main kernel: persistent, 4 groups x 4 warps, ring X ----------------
__global__ __launch_bounds__(512, 1)
void pcnn_hmma_kernel(const int* __restrict__ char_ids,
                      const int* __restrict__ pos_e1,
                      const int* __restrict__ pos_e2,
                      const float* __restrict__ conv_b)
{
    extern __shared__ char smem[];
    const uint32_t sbA = (smem_u32(smem) + 255u) & ~255u;   // 256B-aligned base
    const int tid  = threadIdx.x;
    const int g    = tid >> 7;          // group 0..3
    const int gtid = tid & 127;
    const int wf   = gtid >> 5;         // f-tile within group (32f each)
    const int lane = tid & 31;

    const uint32_t mbar = sbA + MBAR_OFF;

    // resident W copy (96 KB, once per CTA for the whole kernel)
    if (tid == 0) {
        MBAR_INIT(mbar, 1);
        MBAR_EXPECT_TX(mbar, WS_BYTES);
        BULK_G2S(sbA + WS_OFF, (uint64_t)&g_Wh[0], WS_BYTES, mbar);
    }
    __syncthreads();

    // epilogue constants
    const int rowc = lane >> 2;
    const int colc = (lane & 3) * 2;
    float biasv[4];
    #pragma unroll
    for (int i = 0; i < 4; ++i)
        biasv[i] = conv_b[wf * 32 + (i >> 1) * 16 + rowc + (i & 1) * 8];
    float rm[4][3];
    #pragma unroll
    for (int i = 0; i < 4; ++i) { rm[i][0] = 0.f; rm[i][1] = 0.f; rm[i][2] = 0.f; }

    // ldmatrix lane-address components
    const int a_row = lane & 15;
    const int a_cg  = lane >> 4;
    const int b_r  = (lane & 7) + ((lane >> 4) << 3);
    const int b_kc = (lane >> 3) & 1;

    const uint32_t ringB = sbA + (uint32_t)XR_OFF(g);

    // A address keys (XOR-folded swizzle); + k*32768 added per tap
    uint32_t aK[2];
    #pragma unroll
    for (int mt = 0; mt < 2; ++mt) {
        const int f = wf * 32 + mt * 16 + a_row;
        aK[mt] = (sbA + WS_OFF + (uint32_t)f * 256u) ^ ((uint32_t)(f & 7) << 4);
    }

    // full gather: rows l in [L0-1, L0+64] (66 rows) of batch bb
    #define ISSUE_FULL(bb, L0v) do { \
        _Pragma("unroll") \
        for (int it = 0; it < 9; ++it) { \
            const int v = gtid + it * 128; \
            if (v < 66 * 16) { \
                const int p = v >> 4, c = v & 15; \
                const int l = (L0v) - 1 + p; \
                const int slot = ((L0v) + p) % R_RING; \
                const int ok = (l >= 0 && l < SEQ); \
                const int id = __ldg(&char_ids[(bb) * SEQ + (ok ? l : 0)]); \
                const uint64_t src = (uint64_t)&g_EmbH[(size_t)id * EMB] + (uint32_t)(c << 4); \
                const uint32_t dst = ringB + (uint32_t)slot * 256u + (uint32_t)((c ^ (slot & 7)) << 4); \
                CP_ASYNC16(dst, src, ok ? 16 : 0); \
            } \
        } \
        CP_COMMIT(); \
    } while (0)

    // incremental gather for next block at L0n (same batch): rows (L0n, L0n+64]
    #define ISSUE_INCR(bb, L0n) do { \
        _Pragma("unroll") \
        for (int it = 0; it < 8; ++it) { \
            const int v = gtid + it * 128; \
            const int p = v >> 4, c = v & 15; \
            const int l = (L0n) + 1 + p; \
            const int slot = (l + 1) % R_RING; \
            const int ok = (l < SEQ); \
            const int id = __ldg(&char_ids[(bb) * SEQ + (ok ? l : 0)]); \
            const uint64_t src = (uint64_t)&g_EmbH[(size_t)id * EMB] + (uint32_t)(c << 4); \
            const uint32_t dst = ringB + (uint32_t)slot * 256u + (uint32_t)((c ^ (slot & 7)) << 4); \
            CP_ASYNC16(dst, src, ok ? 16 : 0); \
        } \
        CP_COMMIT(); \
    } while (0)

    // static contiguous-range schedule over 4096 blocks
    const int S   = (int)gridDim.x * 4;
    const int sid = blockIdx.x * 4 + g;
    const int bas = NBLK / S;
    const int rem = NBLK - bas * S;
    int u        = sid * bas + (sid < rem ? sid : rem);
    const int u1 = u + bas + (sid < rem ? 1 : 0);

    if (u < u1) ISSUE_FULL(u >> 3, (u & 7) << 6);
    CP_WAIT0();
    MBAR_WAIT(mbar, 0u);
    GBAR(g);

    while (u < u1) {
        const int batch = u >> 3;
        const int L0 = (u & 7) << 6;

        const int p1 = __ldg(&pos_e1[batch]), p2 = __ldg(&pos_e2[batch]);
        int e1 = min(p1, p2), e2 = max(p1, p2);
        if (e1 == e2) e2 = min(e1 + 1, SEQ);
        const int m1hi = max(e1, 1);
        const int m3lo = min(e2, SEQ - 1);

        const int nu = u + 1;
        const bool nvalid = (nu < u1);
        const bool same = nvalid && ((nu >> 3) == batch);
        if (same) ISSUE_INCR(batch, (nu & 7) << 6);   // disjoint from live window mod 130

        // ---- GEMM: C[32f x 64l] += sum_k sum_e W[k] * X(ring rows, shifted by k) ----
        float acc[2][8][4];
        #pragma unroll
        for (int mt = 0; mt < 2; ++mt)
            #pragma unroll
            for (int nt = 0; nt < 8; ++nt)
                #pragma unroll
                for (int i = 0; i < 4; ++i) acc[mt][nt][i] = 0.f;

        #pragma unroll
        for (int k = 0; k < KW; ++k) {
            const uint32_t aB0 = aK[0] + (uint32_t)k * 32768u;
            const uint32_t aB1 = aK[1] + (uint32_t)k * 32768u;
            uint32_t rB[4];
            #pragma unroll
            for (int q = 0; q < 4; ++q) {
                const int ur = L0 + q * 16 + b_r + k;   // = l+1, l = seq row of frag
                const int slot = ur % R_RING;
                rB[q] = (ringB + (uint32_t)slot * 256u) ^ ((uint32_t)(slot & 7) << 4);
            }

            #pragma unroll
            for (int ec = 0; ec < 8; ++ec) {
                const uint32_t ax = (uint32_t)((ec * 2 + a_cg) << 4);
                const uint32_t bx = (uint32_t)((ec * 2 + b_kc) << 4);
                uint32_t a0[4], a1[4], bb[4][4];
                LDSM_X4(a0[0], a0[1], a0[2], a0[3], aB0 ^ ax);
                LDSM_X4(a1[0], a1[1], a1[2], a1[3], aB1 ^ ax);
                #pragma unroll
                for (int q = 0; q < 4; ++q)
                    LDSM_X4(bb[q][0], bb[q][1], bb[q][2], bb[q][3], rB[q] ^ bx);

                #pragma unroll
                for (int q = 0; q < 4; ++q) {
                    MMA16816(acc[0][2 * q],     a0, bb[q][0], bb[q][1]);
                    MMA16816(acc[0][2 * q + 1], a0, bb[q][2], bb[q][3]);
                    MMA16816(acc[1][2 * q],     a1, bb[q][0], bb[q][1]);
                    MMA16816(acc[1][2 * q + 1], a1, bb[q][2], bb[q][3]);
                }
            }
        }

        // ---- epilogue: bias + ReLU + running segment max ----
        #pragma unroll
        for (int mt = 0; mt < 2; ++mt)
            #pragma unroll
            for (int nt = 0; nt < 8; ++nt)
                #pragma unroll
                for (int e = 0; e < 4; ++e) {
                    const int half = e >> 1;
                    const int idx = mt * 2 + half;
                    float v = acc[mt][nt][e] + biasv[idx];
                    v = fmaxf(v, 0.f);
                    const int l = L0 + nt * 8 + colc + (e & 1);
                    if (l < m1hi)          rm[idx][0] = fmaxf(rm[idx][0], v);
                    if (l >= e1 && l < e2) rm[idx][1] = fmaxf(rm[idx][1], v);
                    if (l >= m3lo)         rm[idx][2] = fmaxf(rm[idx][2], v);
                }

        // ---- flush maxima when this batch's blocks are done for this slot ----
        if (!same) {
            unsigned* pb_ = &g_Pool[batch * 3 * FILT];
            #pragma unroll
            for (int i = 0; i < 4; ++i) {
                const int f = wf * 32 + (i >> 1) * 16 + rowc + (i & 1) * 8;
                if (rm[i][0] > 0.f) atomicMax(&pb_[f],            __float_as_uint(rm[i][0]));
                if (rm[i][1] > 0.f) atomicMax(&pb_[FILT + f],     __float_as_uint(rm[i][1]));
                if (rm[i][2] > 0.f) atomicMax(&pb_[2 * FILT + f], __float_as_uint(rm[i][2]));
                rm[i][0] = 0.f; rm[i][1] = 0.f; rm[i][2] = 0.f;
            }
        }

        CP_WAIT0();
        GBAR(g);     // group done reading window; prefetched rows visible

        if (nvalid && !same) {   // batch boundary: gather fresh window now
            ISSUE_FULL(nu >> 3, (nu & 7) << 6);
            CP_WAIT0();
            GBAR(g);
        }
        u = nu;
    }
}

// ---------------- FC kernel ----------------
__global__ __launch_bounds__(64, 8)
void fc_kernel(const float* __restrict__ fc_w,
               const float* __restrict__ fc_b,
               float* __restrict__ out) {
    const int b = blockIdx.x;
    const int c = threadIdx.x;
    if (c < NCLS) {
        float a = fc_b[c];
        const unsigned* pp = &g_Pool[b * 3 * FILT];
        const float* wv = &fc_w[c * 3 * FILT];
        #pragma unroll 8
        for (int i = 0; i < 3 * FILT; ++i)
            a = fmaf(__uint_as_float(pp[i]), __ldg(&wv[i]), a);
        out[b * NCLS + c] = a;
    }
}

extern "C" void kernel_launch(void* const* d_in, const int* in_sizes, int n_in,
                              void* d_out, int out_size) {
    const int*   char_ids = (const int*)  d_in[0];
    const int*   pos_e1   = (const int*)  d_in[1];
    const int*   pos_e2   = (const int*)  d_in[2];
    const float* emb      = (const float*)d_in[3];
    const float* conv_w   = (const float*)d_in[4];
    const float* conv_b   = (const float*)d_in[5];
    const float* fc_w     = (const float*)d_in[6];
    const float* fc_b     = (const float*)d_in[7];
    float* out = (float*)d_out;

    cudaFuncSetAttribute(pcnn_hmma_kernel,
                         cudaFuncAttributeMaxDynamicSharedMemorySize, SMEM_BYTES);

    prep_kernel<<<(VOCAB * EMB / 4 + 255) / 256, 256>>>(conv_w, emb);
    pcnn_hmma_kernel<<<152, 512, SMEM_BYTES>>>(char_ids, pos_e1, pos_e2, conv_b);
    fc_kernel<<<BATCH, 64>>>(fc_w, fc_b, out);
}

// round 17
// speedup vs baseline: 1.0349x; 1.0349x over previous
#include <cuda_runtime.h>
#include <cuda_fp16.h>
#include <cstdint>

#define BATCH 512
#define SEQ   512
#define EMB   128
#define FILT  128
#define KW    3
#define NCLS  53
#define VOCAB 21128
#define NUNITS (BATCH * 4)        // unit = quarter batch = one 128-l pass

// ---- smem layout (bytes) ----
#define WS_OFF   0                 // W fp16 [3][128 f][128 e], resident, chunk-swizzled
#define WS_BYTES 98304
#define XS_BYTES 33280             // one X buffer: 130 rows x 256B
#define XS_OFF(g, d) (WS_BYTES + ((g) * 2 + (d)) * XS_BYTES)   // 4 buffers
#define MBAR_OFF 231424
#define SMEM_BYTES 231488          // <= 232448 (227KB opt-in), 1 CTA/SM

// pre-swizzled fp16 weights: g_Wh[k*16384 + f*128 + ((e>>3)^(f&7))*8 + (e&7)]
__device__ __align__(16) __half g_Wh[KW * FILT * EMB];
// fp16 embedding table (row-major, 256B rows)
__device__ __align__(16) __half g_EmbH[VOCAB * EMB];
// global segment-max pool: [batch][3][128] as float bits (zeroed in prep)
__device__ __align__(16) unsigned g_Pool[BATCH * 3 * FILT];

__device__ __forceinline__ uint32_t smem_u32(const void* p) {
    uint32_t a;
    asm("{ .reg .u64 t; cvta.to.shared.u64 t, %1; cvt.u32.u64 %0, t; }" : "=r"(a) : "l"(p));
    return a;
}

#define MBAR_INIT(a, c) asm volatile("mbarrier.init.shared.b64 [%0], %1;" :: "r"(a), "r"(c) : "memory")
#define MBAR_EXPECT_TX(a, n) asm volatile("mbarrier.arrive.expect_tx.shared.b64 _, [%0], %1;" :: "r"(a), "r"(n) : "memory")
#define MBAR_WAIT(a, p) do { \
    uint32_t _m = (a); uint32_t _p = (p); \
    asm volatile("{\n\t.reg .pred P;\n\tWL_%=:\n\t" \
        "mbarrier.try_wait.parity.acquire.cta.shared::cta.b64 P, [%0], %1, 0x989680;\n\t" \
        "@P bra.uni WD_%=;\n\tbra.uni WL_%=;\n\tWD_%=:\n\t}" :: "r"(_m), "r"(_p) : "memory"); \
} while (0)

#define BULK_G2S(dst, src, nbytes, mbar) \
    asm volatile("cp.async.bulk.shared::cluster.global.mbarrier::complete_tx::bytes [%0], [%1], %2, [%3];" \
        :: "r"(dst), "l"(src), "r"(nbytes), "r"(mbar) : "memory")

#define CP_ASYNC16(dst, src, srcsz) \
    asm volatile("cp.async.ca.shared.global [%0], [%1], 16, %2;" \
        :: "r"(dst), "l"(src), "r"(srcsz) : "memory")
#define CP_COMMIT() asm volatile("cp.async.commit_group;" ::: "memory")
#define CP_WAIT0()  asm volatile("cp.async.wait_group 0;" ::: "memory")

#define GBAR(g) asm volatile("bar.sync %0, 256;" :: "r"((g) + 1) : "memory")

#define LDSM_X4(r0, r1, r2, r3, a) \
    asm volatile("ldmatrix.sync.aligned.m8n8.x4.shared.b16 {%0,%1,%2,%3}, [%4];" \
        : "=r"(r0), "=r"(r1), "=r"(r2), "=r"(r3) : "r"(a))

#define MMA16816(c, a, b0, b1) \
    asm volatile("mma.sync.aligned.m16n8k16.row.col.f32.f16.f16.f32 " \
        "{%0,%1,%2,%3}, {%4,%5,%6,%7}, {%8,%9}, {%0,%1,%2,%3};" \
        : "+f"((c)[0]), "+f"((c)[1]), "+f"((c)[2]), "+f"((c)[3]) \
        : "r"((a)[0]), "r"((a)[1]), "r"((a)[2]), "r"((a)[3]), "r"(b0), "r"(b1))

// ---------------- combined prep: W swizzle + emb fp16 + pool zero ----------------
__global__ void prep_kernel(const float* __restrict__ conv_w,
                            const float* __restrict__ emb) {
    int idx = blockIdx.x * blockDim.x + threadIdx.x;
    if (idx < KW * FILT * EMB) {       // 49152: weight convert+swizzle
        int k = idx / (FILT * EMB);
        int rem = idx - k * FILT * EMB;
        int f = rem >> 7, e = rem & 127;
        float w = conv_w[(f * EMB + e) * KW + k];
        int dst = k * 16384 + f * 128 + (((e >> 3) ^ (f & 7)) << 3) + (e & 7);
        g_Wh[dst] = __float2half_rn(w);
        ((uint4*)g_Pool)[idx] = make_uint4(0u, 0u, 0u, 0u);  // 49152 uint4 = pool
    }
    if (idx < VOCAB * EMB / 8) {       // emb fp32 -> fp16, 32B load / 16B store
        const float4 x0 = __ldg((const float4*)emb + 2 * idx);
        const float4 x1 = __ldg((const float4*)emb + 2 * idx + 1);
        __half2 h0 = __floats2half2_rn(x0.x, x0.y);
        __half2 h1 = __floats2half2_rn(x0.z, x0.w);
        __half2 h2 = __floats2half2_rn(x1.x, x1.y);
        __half2 h3 = __floats2half2_rn(x1.z, x1.w);
        uint4 st;
        st.x = *(uint32_t*)&h0; st.y = *(uint32_t*)&h1;
        st.z = *(uint32_t*)&h2; st.w = *(uint32_t*)&h3;
        *((uint4*)g_EmbH + idx) = st;
    }
}

// ---------------- main kernel: persistent, 2 groups/CTA, unit = 128-l pass ----------------
__global__ __launch_bounds__(512, 1)
void pcnn_hmma_kernel(const int* __restrict__ char_ids,
                      const int* __restrict__ pos_e1,
                      const int* __restrict__ pos_e2,
                      const float* __restrict__ conv_b)
{
    extern __shared__ char smem[];
    const uint32_t sb = smem_u32(smem);
    const int tid  = threadIdx.x;
    const int g    = tid >> 8;          // group 0/1
    const int gtid = tid & 255;
    const int w    = gtid >> 5;
    const int lane = tid & 31;

    const int wf = w & 3;   // f-tile: f in [wf*32, +32)
    const int wl = w >> 2;  // l-tile: l_local in [wl*64, +64)

    const uint32_t mbar = sb + MBAR_OFF;

    // resident W copy (96 KB, once per CTA for the whole kernel)
    if (tid == 0) {
        MBAR_INIT(mbar, 1);
        MBAR_EXPECT_TX(mbar, WS_BYTES);
        BULK_G2S(sb + WS_OFF, (uint64_t)&g_Wh[0], WS_BYTES, mbar);
    }
    __syncthreads();

    // epilogue constants (batch-independent)
    const int rowc = lane >> 2;
    const int colc = (lane & 3) * 2;
    float biasv[4];
    #pragma unroll
    for (int i = 0; i < 4; ++i)
        biasv[i] = conv_b[wf * 32 + (i >> 1) * 16 + rowc + (i & 1) * 8];
    float rm[4][3];
    #pragma unroll
    for (int i = 0; i < 4; ++i) { rm[i][0] = 0.f; rm[i][1] = 0.f; rm[i][2] = 0.f; }

    // ldmatrix lane-address components
    const int a_row = lane & 15;
    const int a_cg  = lane >> 4;
    const int b_r  = (lane & 7) + ((lane >> 4) << 3);
    const int b_kc = (lane >> 3) & 1;

    const uint32_t xsb[2] = {sb + (uint32_t)XS_OFF(g, 0), sb + (uint32_t)XS_OFF(g, 1)};

    // async gather of tile (batch bb, l-base pb) into buffer d: 130 rows x 16 chunks
    #define ISSUE_GATHER(bb, pb, d) do { \
        _Pragma("unroll") \
        for (int it = 0; it < 9; ++it) { \
            const int v = gtid + it * 256; \
            if (v < 130 * 16) { \
                const int p = v >> 4, c = v & 15; \
                const int l = (pb) + p - 1; \
                const int ok = (l >= 0 && l < SEQ); \
                const int lc = ok ? l : 0; \
                const int id = __ldg(&char_ids[(bb) * SEQ + lc]); \
                const uint64_t src = (uint64_t)&g_EmbH[(size_t)id * EMB] + (uint32_t)(c << 4); \
                const uint32_t dst = xsb[d] + (uint32_t)(p * 256 + ((c ^ (p & 7)) << 4)); \
                CP_ASYNC16(dst, src, ok ? 16 : 0); \
            } \
        } \
        CP_COMMIT(); \
    } while (0)

    // contiguous-range schedule: slot handles units [u0, u1)
    const int S   = (int)gridDim.x * 2;
    const int sid = blockIdx.x * 2 + g;
    const int bas = NUNITS / S;
    const int rmd = NUNITS - bas * S;
    int u        = sid * bas + (sid < rmd ? sid : rmd);
    const int u1 = u + bas + (sid < rmd ? 1 : 0);

    if (u < u1) ISSUE_GATHER(u >> 2, (u & 3) * 128, 0);
    CP_WAIT0();
    MBAR_WAIT(mbar, 0u);
    GBAR(g);

    // segment bounds, loaded on batch change
    int curb = -1, e1 = 0, e2 = 0, m1hi = 0, m3lo = 0;

    int buf = 0;
    while (u < u1) {
        const int batch = u >> 2;
        const int pbase = (u & 3) * 128;

        if (batch != curb) {
            curb = batch;
            const int p1 = __ldg(&pos_e1[batch]), p2 = __ldg(&pos_e2[batch]);
            e1 = min(p1, p2); e2 = max(p1, p2);
            if (e1 == e2) e2 = min(e1 + 1, SEQ);
            m1hi = max(e1, 1);
            m3lo = min(e2, SEQ - 1);
        }

        // prefetch next unit (always full gather; never drains)
        const int nu = u + 1;
        const bool nvalid = (nu < u1);
        if (nvalid) ISSUE_GATHER(nu >> 2, (nu & 3) * 128, buf ^ 1);

        // ---- GEMM: C[32f x 64l] += sum_k sum_e W[k] * X(shifted by k) ----
        float acc[2][8][4];
        #pragma unroll
        for (int mt = 0; mt < 2; ++mt)
            #pragma unroll
            for (int nt = 0; nt < 8; ++nt)
                #pragma unroll
                for (int i = 0; i < 4; ++i) acc[mt][nt][i] = 0.f;

        #pragma unroll
        for (int k = 0; k < KW; ++k) {
            const uint32_t wsBase = sb + WS_OFF + (uint32_t)k * 32768u;
            uint32_t aBase[2]; int aS[2];
            #pragma unroll
            for (int mt = 0; mt < 2; ++mt) {
                const int f = wf * 32 + mt * 16 + a_row;
                aBase[mt] = wsBase + (uint32_t)f * 256u;
                aS[mt] = f & 7;
            }
            const int p0 = wl * 64 + b_r + k;
            const uint32_t bBase = xsb[buf] + (uint32_t)p0 * 256u;
            const int bS = p0 & 7;

            #pragma unroll
            for (int ec = 0; ec < 8; ++ec) {
                uint32_t a0[4], a1[4], bb[4][4];
                const int ca = ec * 2 + a_cg;
                const int cb = ec * 2 + b_kc;
                LDSM_X4(a0[0], a0[1], a0[2], a0[3],
                        aBase[0] + (uint32_t)((ca ^ aS[0]) << 4));
                LDSM_X4(a1[0], a1[1], a1[2], a1[3],
                        aBase[1] + (uint32_t)((ca ^ aS[1]) << 4));
                const uint32_t bsw = (uint32_t)((cb ^ bS) << 4);
                #pragma unroll
                for (int q = 0; q < 4; ++q)
                    LDSM_X4(bb[q][0], bb[q][1], bb[q][2], bb[q][3],
                            bBase + (uint32_t)(q * 4096) + bsw);

                #pragma unroll
                for (int q = 0; q < 4; ++q) {
                    MMA16816(acc[0][2 * q],     a0, bb[q][0], bb[q][1]);
                    MMA16816(acc[0][2 * q + 1], a0, bb[q][2], bb[q][3]);
                    MMA16816(acc[1][2 * q],     a1, bb[q][0], bb[q][1]);
                    MMA16816(acc[1][2 * q + 1], a1, bb[q][2], bb[q][3]);
                }
            }
        }

        // ---- epilogue: bias + ReLU + running segment max ----
        #pragma unroll
        for (int mt = 0; mt < 2; ++mt)
            #pragma unroll
            for (int nt = 0; nt < 8; ++nt)
                #pragma unroll
                for (int e = 0; e < 4; ++e) {
                    const int half = e >> 1;
                    const int idx = mt * 2 + half;
                    float v = acc[mt][nt][e] + biasv[idx];
                    v = fmaxf(v, 0.f);
                    const int l = pbase + wl * 64 + nt * 8 + colc + (e & 1);
                    if (l < m1hi)          rm[idx][0] = fmaxf(rm[idx][0], v);
                    if (l >= e1 && l < e2) rm[idx][1] = fmaxf(rm[idx][1], v);
                    if (l >= m3lo)         rm[idx][2] = fmaxf(rm[idx][2], v);
                }

        // ---- flush maxima only when leaving this batch (or at range end) ----
        if (!nvalid || (nu >> 2) != batch) {
            unsigned* pb_ = &g_Pool[batch * 3 * FILT];
            #pragma unroll
            for (int i = 0; i < 4; ++i) {
                const int f = wf * 32 + (i >> 1) * 16 + rowc + (i & 1) * 8;
                if (rm[i][0] > 0.f) atomicMax(&pb_[f],            __float_as_uint(rm[i][0]));
                if (rm[i][1] > 0.f) atomicMax(&pb_[FILT + f],     __float_as_uint(rm[i][1]));
                if (rm[i][2] > 0.f) atomicMax(&pb_[2 * FILT + f], __float_as_uint(rm[i][2]));
                rm[i][0] = 0.f; rm[i][1] = 0.f; rm[i][2] = 0.f;
            }
        }

        CP_WAIT0();   // next buffer landed
        GBAR(g);      // group done reading buf; cp.async stores visible
        buf ^= 1;
        u = nu;
    }
}

// ---------------- FC kernel: out[b][c] = pooled . fc_w[c] + fc_b[c] ----------------
__global__ __launch_bounds__(64, 8)
void fc_kernel(const float* __restrict__ fc_w,
               const float* __restrict__ fc_b,
               float* __restrict__ out) {
    const int b = blockIdx.x;
    const int c = threadIdx.x;
    if (c < NCLS) {
        float a = fc_b[c];
        const unsigned* pp = &g_Pool[b * 3 * FILT];
        const float* wv = &fc_w[c * 3 * FILT];
        #pragma unroll 8
        for (int i = 0; i < 3 * FILT; ++i)
            a = fmaf(__uint_as_float(pp[i]), __ldg(&wv[i]), a);
        out[b * NCLS + c] = a;
    }
}

extern "C" void kernel_launch(void* const* d_in, const int* in_sizes, int n_in,
                              void* d_out, int out_size) {
    const int*   char_ids = (const int*)  d_in[0];
    const int*   pos_e1   = (const int*)  d_in[1];
    const int*   pos_e2   = (const int*)  d_in[2];
    const float* emb      = (const float*)d_in[3];
    const float* conv_w   = (const float*)d_in[4];
    const float* conv_b   = (const float*)d_in[5];
    const float* fc_w     = (const float*)d_in[6];
    const float* fc_b     = (const float*)d_in[7];
    float* out = (float*)d_out;

    cudaFuncSetAttribute(pcnn_hmma_kernel,
                         cudaFuncAttributeMaxDynamicSharedMemorySize, SMEM_BYTES);

    prep_kernel<<<(VOCAB * EMB / 4 + 255) / 256, 256>>>(conv_w, emb);
    pcnn_hmma_kernel<<<152, 512, SMEM_BYTES>>>(char_ids, pos_e1, pos_e2, conv_b);
    fc_kernel<<<BATCH, 64>>>(fc_w, fc_b, out);
}